// round 1
// baseline (speedup 1.0000x reference)
#include <cuda_runtime.h>
#include <math.h>
#include <stdint.h>

#define DIM       128
#define NSPECIAL  4
#define MAX_POS   8192
#define TM        64          // tokens per CTA (kernel 2)
#define TL        128         // latents per tile
#define THREADS2  256
#define LSTRIDE   132         // padded smem row stride (floats)
#define NEG_BIG   (-1e30f)

// scratch: lang embeddings per output position (tanh(bag)), special rows = 0
__device__ float g_lang[MAX_POS * DIM];

// ---------------------------------------------------------------------------
// Kernel 1: per-position EmbeddingBag(sum) + tanh
// grid = n_pos blocks, 128 threads (one per dim)
// ---------------------------------------------------------------------------
__global__ void bag_kernel(const float* __restrict__ ngram_emb,
                           const int*   __restrict__ ngram_ids,
                           const int*   __restrict__ ngram_offsets,
                           const int*   __restrict__ x,
                           int n_pos, int n_ngram_total, int n_words)
{
    int pos = blockIdx.x;
    if (pos >= n_pos) return;
    int d = threadIdx.x;
    int t = x[pos];
    float val = 0.0f;
    if (t >= NSPECIAL) {
        int v   = t - NSPECIAL;
        int off = ngram_offsets[v];
        int end = (v + 1 < n_words) ? ngram_offsets[v + 1] : n_ngram_total;
        float acc = 0.0f;
        for (int j = off; j < end; ++j) {
            int id = ngram_ids[j];                  // uniform across block -> broadcast
            acc += ngram_emb[(size_t)id * DIM + d]; // coalesced 512B row
        }
        val = tanhf(acc);
    }
    g_lang[pos * DIM + d] = val;
}

// ---------------------------------------------------------------------------
// Kernel 2: flash-style latent attention + epilogue gather
//   For each token row r: s_l = <lang_r, L_l>;  p = softmax(s);  o = p @ L
//   out = lang + o  (or special_emb for special tokens)
// CTA: 64 tokens; 256 threads as 16(tx latent groups) x 16(ty token groups)
// micro-tile per thread: 4 tokens x 8 latents
// ---------------------------------------------------------------------------
__global__ __launch_bounds__(THREADS2)
void attn_kernel(const float* __restrict__ latent,   // [n_latent][128]
                 const float* __restrict__ special,  // [4][128]
                 const int*   __restrict__ x,
                 float*       __restrict__ out,
                 int n_pos, int n_latent)
{
    extern __shared__ float smem[];
    float* s_lang = smem;                       // TM * LSTRIDE
    float* s_L    = smem + TM * LSTRIDE;        // TL * LSTRIDE
    float* s_P    = s_L  + TL * LSTRIDE;        // TM * LSTRIDE

    const int tid = threadIdx.x;
    const int tx  = tid & 15;    // latent group: latents tx + 16*j, j=0..7
    const int ty  = tid >> 4;    // token group:  tokens ty*4 + i, i=0..3
    const int ty4 = ty << 2;
    const int pos0 = blockIdx.x * TM;

    // ---- load lang tile [TM x 128] ----
    for (int k = tid; k < TM * (DIM / 4); k += THREADS2) {
        int r = k >> 5, c = k & 31;
        float4 v = make_float4(0.f, 0.f, 0.f, 0.f);
        if (pos0 + r < n_pos)
            v = ((const float4*)(g_lang + (size_t)(pos0 + r) * DIM))[c];
        *(float4*)(s_lang + r * LSTRIDE + (c << 2)) = v;
    }

    float o[4][8];
    float m[4], z[4];
#pragma unroll
    for (int i = 0; i < 4; ++i) {
        m[i] = NEG_BIG; z[i] = 0.0f;
#pragma unroll
        for (int c = 0; c < 8; ++c) o[i][c] = 0.0f;
    }
    __syncthreads();

    const int n_tiles = (n_latent + TL - 1) / TL;
    for (int tile = 0; tile < n_tiles; ++tile) {
        const int l0 = tile * TL;

        // ---- load L tile [TL x 128] (zero-pad past n_latent) ----
        for (int k = tid; k < TL * (DIM / 4); k += THREADS2) {
            int r = k >> 5, c = k & 31;
            int gl = l0 + r;
            float4 v = make_float4(0.f, 0.f, 0.f, 0.f);
            if (gl < n_latent)
                v = ((const float4*)(latent + (size_t)gl * DIM))[c];
            *(float4*)(s_L + r * LSTRIDE + (c << 2)) = v;
        }
        __syncthreads();

        // ---- phase 1: 4x8 score micro-tile over d ----
        float s[4][8];
#pragma unroll
        for (int i = 0; i < 4; ++i)
#pragma unroll
            for (int j = 0; j < 8; ++j) s[i][j] = 0.0f;

        for (int d = 0; d < DIM; d += 4) {
            float4 a0 = *(const float4*)(s_lang + (ty4 + 0) * LSTRIDE + d);
            float4 a1 = *(const float4*)(s_lang + (ty4 + 1) * LSTRIDE + d);
            float4 a2 = *(const float4*)(s_lang + (ty4 + 2) * LSTRIDE + d);
            float4 a3 = *(const float4*)(s_lang + (ty4 + 3) * LSTRIDE + d);
#pragma unroll
            for (int jh = 0; jh < 2; ++jh) {
#pragma unroll
                for (int j = 0; j < 4; ++j) {
                    int jj = (jh << 2) + j;
                    float4 b = *(const float4*)(s_L + (tx + (jj << 4)) * LSTRIDE + d);
                    s[0][jj] += a0.x * b.x; s[0][jj] += a0.y * b.y;
                    s[0][jj] += a0.z * b.z; s[0][jj] += a0.w * b.w;
                    s[1][jj] += a1.x * b.x; s[1][jj] += a1.y * b.y;
                    s[1][jj] += a1.z * b.z; s[1][jj] += a1.w * b.w;
                    s[2][jj] += a2.x * b.x; s[2][jj] += a2.y * b.y;
                    s[2][jj] += a2.z * b.z; s[2][jj] += a2.w * b.w;
                    s[3][jj] += a3.x * b.x; s[3][jj] += a3.y * b.y;
                    s[3][jj] += a3.z * b.z; s[3][jj] += a3.w * b.w;
                }
            }
        }

        // mask latents past n_latent
#pragma unroll
        for (int j = 0; j < 8; ++j) {
            if (l0 + tx + (j << 4) >= n_latent) {
#pragma unroll
                for (int i = 0; i < 4; ++i) s[i][j] = NEG_BIG;
            }
        }

        // ---- online softmax update (reduce over 16 tx lanes) ----
#pragma unroll
        for (int i = 0; i < 4; ++i) {
            float mt = s[i][0];
#pragma unroll
            for (int j = 1; j < 8; ++j) mt = fmaxf(mt, s[i][j]);
            mt = fmaxf(mt, __shfl_xor_sync(0xffffffffu, mt, 1));
            mt = fmaxf(mt, __shfl_xor_sync(0xffffffffu, mt, 2));
            mt = fmaxf(mt, __shfl_xor_sync(0xffffffffu, mt, 4));
            mt = fmaxf(mt, __shfl_xor_sync(0xffffffffu, mt, 8));

            float mnew = fmaxf(m[i], mt);
            float corr = __expf(m[i] - mnew);   // m=NEG_BIG first -> 0
            float zloc = 0.0f;
#pragma unroll
            for (int j = 0; j < 8; ++j) {
                float p = __expf(s[i][j] - mnew);
                s[i][j] = p;
                zloc += p;
            }
            zloc += __shfl_xor_sync(0xffffffffu, zloc, 1);
            zloc += __shfl_xor_sync(0xffffffffu, zloc, 2);
            zloc += __shfl_xor_sync(0xffffffffu, zloc, 4);
            zloc += __shfl_xor_sync(0xffffffffu, zloc, 8);

            z[i] = z[i] * corr + zloc;
            m[i] = mnew;
#pragma unroll
            for (int c = 0; c < 8; ++c) o[i][c] *= corr;
        }

        // ---- stage P tile to smem ----
#pragma unroll
        for (int i = 0; i < 4; ++i)
#pragma unroll
            for (int j = 0; j < 8; ++j)
                s_P[(ty4 + i) * LSTRIDE + tx + (j << 4)] = s[i][j];
        __syncthreads();

        // ---- phase 2: o += P @ L  (thread: 4 tokens x 8 dims) ----
        const int dbase = tx << 3;
#pragma unroll 4
        for (int l = 0; l < TL; ++l) {
            float4 b0 = *(const float4*)(s_L + l * LSTRIDE + dbase);
            float4 b1 = *(const float4*)(s_L + l * LSTRIDE + dbase + 4);
#pragma unroll
            for (int i = 0; i < 4; ++i) {
                float p = s_P[(ty4 + i) * LSTRIDE + l];
                o[i][0] += p * b0.x; o[i][1] += p * b0.y;
                o[i][2] += p * b0.z; o[i][3] += p * b0.w;
                o[i][4] += p * b1.x; o[i][5] += p * b1.y;
                o[i][6] += p * b1.z; o[i][7] += p * b1.w;
            }
        }
        __syncthreads();   // protect s_L / s_P before next tile overwrite
    }

    // ---- epilogue: out = lang + o / z, or special row ----
    const int dbase = tx << 3;
#pragma unroll
    for (int i = 0; i < 4; ++i) {
        int r = ty4 + i;
        int pos = pos0 + r;
        if (pos >= n_pos) continue;
        int t = x[pos];
        float4 r0, r1;
        if (t < NSPECIAL) {
            r0 = *(const float4*)(special + t * DIM + dbase);
            r1 = *(const float4*)(special + t * DIM + dbase + 4);
        } else {
            float invz = 1.0f / z[i];
            r0.x = s_lang[r * LSTRIDE + dbase + 0] + o[i][0] * invz;
            r0.y = s_lang[r * LSTRIDE + dbase + 1] + o[i][1] * invz;
            r0.z = s_lang[r * LSTRIDE + dbase + 2] + o[i][2] * invz;
            r0.w = s_lang[r * LSTRIDE + dbase + 3] + o[i][3] * invz;
            r1.x = s_lang[r * LSTRIDE + dbase + 4] + o[i][4] * invz;
            r1.y = s_lang[r * LSTRIDE + dbase + 5] + o[i][5] * invz;
            r1.z = s_lang[r * LSTRIDE + dbase + 6] + o[i][6] * invz;
            r1.w = s_lang[r * LSTRIDE + dbase + 7] + o[i][7] * invz;
        }
        *(float4*)(out + (size_t)pos * DIM + dbase)     = r0;
        *(float4*)(out + (size_t)pos * DIM + dbase + 4) = r1;
    }
}

// ---------------------------------------------------------------------------
extern "C" void kernel_launch(void* const* d_in, const int* in_sizes, int n_in,
                              void* d_out, int out_size)
{
    const float* ngram_emb     = (const float*)d_in[0];  // [32001,128]
    const float* latent        = (const float*)d_in[1];  // [10000,128]
    const float* special       = (const float*)d_in[2];  // [4,128]
    const int*   ngram_ids     = (const int*)  d_in[3];  // [832000]
    const int*   ngram_offsets = (const int*)  d_in[4];  // [32000]
    const int*   x             = (const int*)  d_in[5];  // [8192]

    int n_pos    = in_sizes[5];
    int n_words  = in_sizes[4];
    int n_ngtot  = in_sizes[3];
    int n_latent = in_sizes[1] / DIM;
    if (n_pos > MAX_POS) n_pos = MAX_POS;   // scratch bound (problem uses 8192)

    float* out = (float*)d_out;

    bag_kernel<<<n_pos, DIM>>>(ngram_emb, ngram_ids, ngram_offsets, x,
                               n_pos, n_ngtot, n_words);

    const int smem_bytes = (TM + TL + TM) * LSTRIDE * sizeof(float); // 132 KB
    cudaFuncSetAttribute(attn_kernel,
                         cudaFuncAttributeMaxDynamicSharedMemorySize, smem_bytes);
    int grid2 = (n_pos + TM - 1) / TM;
    attn_kernel<<<grid2, THREADS2, smem_bytes>>>(latent, special, x,
                                                 out, n_pos, n_latent);
}

// round 2
// speedup vs baseline: 10.8533x; 10.8533x over previous
#include <cuda_runtime.h>
#include <cuda_bf16.h>
#include <math.h>
#include <stdint.h>

#define DIM       128
#define NSPECIAL  4
#define MAX_POS   8192
#define MAX_LT    80          // max latent tiles of 128
#define STRIDE    136         // smem row stride in bf16 elements (272B, 16B-aligned, conflict-free)
#define NSPLIT    2

// ---- static device scratch (no allocations allowed) ----
__device__ float          g_lang [MAX_POS * DIM];              // fp32 tanh(bag)
__device__ __nv_bfloat16  g_langb[MAX_POS * DIM];              // bf16 copy for MMA
__device__ __nv_bfloat16  g_Lb   [MAX_LT * 128 * DIM];         // bf16 latent, zero-padded
__device__ float          g_O    [NSPLIT][MAX_POS * DIM];      // partial sum exp(s)·L
__device__ float          g_z    [NSPLIT][2][MAX_POS];         // partial sum exp(s), per warp_n

// ---------------------------------------------------------------------------
// PTX helpers
// ---------------------------------------------------------------------------
__device__ __forceinline__ void ldmx4(uint32_t* r, uint32_t addr) {
    asm volatile("ldmatrix.sync.aligned.m8n8.x4.shared.b16 {%0,%1,%2,%3},[%4];\n"
        : "=r"(r[0]), "=r"(r[1]), "=r"(r[2]), "=r"(r[3]) : "r"(addr));
}
__device__ __forceinline__ void ldmx4t(uint32_t* r, uint32_t addr) {
    asm volatile("ldmatrix.sync.aligned.m8n8.x4.trans.shared.b16 {%0,%1,%2,%3},[%4];\n"
        : "=r"(r[0]), "=r"(r[1]), "=r"(r[2]), "=r"(r[3]) : "r"(addr));
}
__device__ __forceinline__ void mma16816(float* d, const uint32_t* a, const uint32_t* b) {
    asm volatile(
        "mma.sync.aligned.m16n8k16.row.col.f32.bf16.bf16.f32 "
        "{%0,%1,%2,%3},{%4,%5,%6,%7},{%8,%9},{%0,%1,%2,%3};\n"
        : "+f"(d[0]), "+f"(d[1]), "+f"(d[2]), "+f"(d[3])
        : "r"(a[0]), "r"(a[1]), "r"(a[2]), "r"(a[3]), "r"(b[0]), "r"(b[1]));
}
__device__ __forceinline__ void cpa16(uint32_t smem_dst, const void* gsrc) {
    asm volatile("cp.async.cg.shared.global [%0], [%1], 16;\n" :: "r"(smem_dst), "l"(gsrc));
}
__device__ __forceinline__ void cpa_commit() {
    asm volatile("cp.async.commit_group;\n" ::: "memory");
}
__device__ __forceinline__ uint32_t pack_bf2(float a, float b) {
    uint16_t x = __bfloat16_as_ushort(__float2bfloat16_rn(a));
    uint16_t y = __bfloat16_as_ushort(__float2bfloat16_rn(b));
    return (uint32_t)x | ((uint32_t)y << 16);
}

// ---------------------------------------------------------------------------
// Kernel 1: EmbeddingBag(sum) + tanh, fp32 + bf16 outputs (padded rows -> 0)
// ---------------------------------------------------------------------------
__global__ void bag_kernel(const float* __restrict__ ngram_emb,
                           const int*   __restrict__ ngram_ids,
                           const int*   __restrict__ ngram_offsets,
                           const int*   __restrict__ x,
                           int n_pos, int n_ngram_total, int n_words)
{
    int pos = blockIdx.x;
    int d   = threadIdx.x;
    float val = 0.0f;
    if (pos < n_pos) {
        int t = x[pos];
        if (t >= NSPECIAL) {
            int v   = t - NSPECIAL;
            int off = ngram_offsets[v];
            int end = (v + 1 < n_words) ? ngram_offsets[v + 1] : n_ngram_total;
            float acc = 0.0f;
            for (int j = off; j < end; ++j) {
                int id = ngram_ids[j];
                acc += ngram_emb[(size_t)id * DIM + d];
            }
            val = tanhf(acc);
        }
    }
    g_lang [pos * DIM + d] = val;
    g_langb[pos * DIM + d] = __float2bfloat16_rn(val);
}

// ---------------------------------------------------------------------------
// Kernel 2: latent -> bf16, zero-pad to full tiles
// ---------------------------------------------------------------------------
__global__ void conv_latent(const float* __restrict__ latent, int n_latent, int rows_pad)
{
    int idx = blockIdx.x * 256 + threadIdx.x;
    if (idx >= rows_pad * DIM) return;
    int r = idx >> 7;
    float v = (r < n_latent) ? latent[idx] : 0.0f;
    g_Lb[idx] = __float2bfloat16_rn(v);
}

// ---------------------------------------------------------------------------
// Kernel 3: fused bf16 MMA attention: O = sum_l exp(s)·L, z = sum_l exp(s)
// CTA = 128 tokens; grid.y = latent split. 256 threads = 8 warps (4x2 grid).
// ---------------------------------------------------------------------------
__global__ __launch_bounds__(256, 1)
void attn_mma(int n_pos, int n_latent)
{
    extern __shared__ __nv_bfloat16 sm[];
    __nv_bfloat16* lang_sm = sm;                       // 128*STRIDE
    __nv_bfloat16* L_sm0   = sm + 128 * STRIDE;        // stage 0
    __nv_bfloat16* L_sm1   = sm + 2 * 128 * STRIDE;    // stage 1
    __nv_bfloat16* P_sm    = sm + 3 * 128 * STRIDE;

    const int tid  = threadIdx.x;
    const int lane = tid & 31;
    const int warp = tid >> 5;
    const int wm   = warp & 3;          // token rows wm*32..+31
    const int wn   = warp >> 2;         // latent cols wn*64..+63 (GEMM1) / dim cols (GEMM2)
    const int pos0 = blockIdx.x * 128;
    const int split = blockIdx.y;

    const int TT   = (n_latent + 127) >> 7;
    const int half = (TT + 1) >> 1;
    const int t0   = split ? half : 0;
    const int cnt  = split ? (TT - half) : half;

    const uint32_t lang_u = (uint32_t)__cvta_generic_to_shared(lang_sm);
    const uint32_t L0_u   = (uint32_t)__cvta_generic_to_shared(L_sm0);
    const uint32_t L1_u   = (uint32_t)__cvta_generic_to_shared(L_sm1);
    const uint32_t P_u    = (uint32_t)__cvta_generic_to_shared(P_sm);

    // ---- load lang tile (128 rows x 256B) ----
    for (int ch = tid; ch < 2048; ch += 256) {
        int r = ch >> 4, c = (ch & 15) << 3;
        *(uint4*)&lang_sm[r * STRIDE + c] = *(const uint4*)&g_langb[(pos0 + r) * DIM + c];
    }

    // ---- prologue: cp.async tile t0 into stage 0 ----
    if (cnt > 0) {
        const __nv_bfloat16* src = &g_Lb[(size_t)t0 * 128 * DIM];
        for (int ch = tid; ch < 2048; ch += 256) {
            int r = ch >> 4, c = (ch & 15) << 3;
            cpa16(L0_u + (r * STRIDE + c) * 2, src + r * DIM + c);
        }
        cpa_commit();
    }

    float o[2][8][4];
    float zacc[2][2];
#pragma unroll
    for (int mi = 0; mi < 2; ++mi) {
        zacc[mi][0] = 0.f; zacc[mi][1] = 0.f;
#pragma unroll
        for (int j = 0; j < 8; ++j)
#pragma unroll
            for (int q = 0; q < 4; ++q) o[mi][j][q] = 0.f;
    }

    const int lr = lane & 15;
    const int lc = (lane & 16) >> 1;   // 0 or 8

    for (int t = 0; t < cnt; ++t) {
        const uint32_t Lst = (t & 1) ? L1_u : L0_u;
        const uint32_t Lnx = (t & 1) ? L0_u : L1_u;

        if (t + 1 < cnt) {
            const __nv_bfloat16* src = &g_Lb[(size_t)(t0 + t + 1) * 128 * DIM];
            for (int ch = tid; ch < 2048; ch += 256) {
                int r = ch >> 4, c = (ch & 15) << 3;
                cpa16(Lnx + (r * STRIDE + c) * 2, src + r * DIM + c);
            }
            cpa_commit();
            asm volatile("cp.async.wait_group 1;\n" ::: "memory");
        } else {
            asm volatile("cp.async.wait_group 0;\n" ::: "memory");
        }
        __syncthreads();

        // ---- GEMM1: S[128 tok x 128 lat] = lang @ L^T ----
        float s[2][8][4];
#pragma unroll
        for (int mi = 0; mi < 2; ++mi)
#pragma unroll
            for (int j = 0; j < 8; ++j)
#pragma unroll
                for (int q = 0; q < 4; ++q) s[mi][j][q] = 0.f;

#pragma unroll
        for (int ks = 0; ks < 8; ++ks) {
            uint32_t a[2][4];
#pragma unroll
            for (int mi = 0; mi < 2; ++mi)
                ldmx4(a[mi], lang_u + ((wm * 32 + mi * 16 + lr) * STRIDE + ks * 16 + lc) * 2);
            uint32_t b[8][2];
#pragma unroll
            for (int ni = 0; ni < 4; ++ni) {
                uint32_t r4[4];
                ldmx4(r4, Lst + ((wn * 64 + ni * 16 + lr) * STRIDE + ks * 16 + lc) * 2);
                b[2 * ni][0] = r4[0]; b[2 * ni][1] = r4[2];
                b[2 * ni + 1][0] = r4[1]; b[2 * ni + 1][1] = r4[3];
            }
#pragma unroll
            for (int mi = 0; mi < 2; ++mi)
#pragma unroll
                for (int j = 0; j < 8; ++j)
                    mma16816(s[mi][j], a[mi], b[j]);
        }

        // ---- exp + tail mask + z accum + P -> smem (bf16) ----
        const int lbase = (t0 + t) * 128;
#pragma unroll
        for (int mi = 0; mi < 2; ++mi) {
            const int r0 = wm * 32 + mi * 16 + (lane >> 2);
#pragma unroll
            for (int j = 0; j < 8; ++j) {
                const int c0 = wn * 64 + j * 8 + ((lane & 3) << 1);
                const int g0 = lbase + c0;
                float p0 = (g0     < n_latent) ? __expf(s[mi][j][0]) : 0.f;
                float p1 = (g0 + 1 < n_latent) ? __expf(s[mi][j][1]) : 0.f;
                float p2 = (g0     < n_latent) ? __expf(s[mi][j][2]) : 0.f;
                float p3 = (g0 + 1 < n_latent) ? __expf(s[mi][j][3]) : 0.f;
                zacc[mi][0] += p0 + p1;
                zacc[mi][1] += p2 + p3;
                *(uint32_t*)&P_sm[ r0      * STRIDE + c0] = pack_bf2(p0, p1);
                *(uint32_t*)&P_sm[(r0 + 8) * STRIDE + c0] = pack_bf2(p2, p3);
            }
        }
        __syncthreads();

        // ---- GEMM2: O += P(tok x lat) @ L(lat x dim), B via ldmatrix.trans ----
#pragma unroll
        for (int ks = 0; ks < 8; ++ks) {
            uint32_t a[2][4];
#pragma unroll
            for (int mi = 0; mi < 2; ++mi)
                ldmx4(a[mi], P_u + ((wm * 32 + mi * 16 + lr) * STRIDE + ks * 16 + lc) * 2);
            uint32_t b[8][2];
#pragma unroll
            for (int ni = 0; ni < 4; ++ni) {
                uint32_t r4[4];
                ldmx4t(r4, Lst + ((ks * 16 + lr) * STRIDE + wn * 64 + ni * 16 + lc) * 2);
                b[2 * ni][0] = r4[0]; b[2 * ni][1] = r4[1];
                b[2 * ni + 1][0] = r4[2]; b[2 * ni + 1][1] = r4[3];
            }
#pragma unroll
            for (int mi = 0; mi < 2; ++mi)
#pragma unroll
                for (int j = 0; j < 8; ++j)
                    mma16816(o[mi][j], a[mi], b[j]);
        }
        __syncthreads();   // P + L stage free for next iteration
    }

    // ---- epilogue: write partial O (fp32) and z ----
#pragma unroll
    for (int mi = 0; mi < 2; ++mi) {
        const int r0 = pos0 + wm * 32 + mi * 16 + (lane >> 2);
#pragma unroll
        for (int j = 0; j < 8; ++j) {
            const int c0 = wn * 64 + j * 8 + ((lane & 3) << 1);
            *(float2*)&g_O[split][ r0      * DIM + c0] = make_float2(o[mi][j][0], o[mi][j][1]);
            *(float2*)&g_O[split][(r0 + 8) * DIM + c0] = make_float2(o[mi][j][2], o[mi][j][3]);
        }
    }
#pragma unroll
    for (int mi = 0; mi < 2; ++mi) {
#pragma unroll
        for (int h = 0; h < 2; ++h) {
            float zz = zacc[mi][h];
            zz += __shfl_xor_sync(0xffffffffu, zz, 1);
            zz += __shfl_xor_sync(0xffffffffu, zz, 2);
            if ((lane & 3) == 0) {
                int r = pos0 + wm * 32 + mi * 16 + (lane >> 2) + h * 8;
                g_z[split][wn][r] = zz;
            }
        }
    }
}

// ---------------------------------------------------------------------------
// Kernel 4: combine partials + fp32 lang add + special override
// ---------------------------------------------------------------------------
__global__ void combine_kernel(const float* __restrict__ special,
                               const int*   __restrict__ x,
                               float*       __restrict__ out,
                               int n_pos)
{
    int pos = blockIdx.x;
    int d   = threadIdx.x;
    if (pos >= n_pos) return;
    int t = x[pos];
    float v;
    if (t < NSPECIAL) {
        v = special[t * DIM + d];
    } else {
        float z = g_z[0][0][pos] + g_z[0][1][pos] + g_z[1][0][pos] + g_z[1][1][pos];
        float O = g_O[0][pos * DIM + d] + g_O[1][pos * DIM + d];
        v = g_lang[pos * DIM + d] + O / z;
    }
    out[pos * DIM + d] = v;
}

// ---------------------------------------------------------------------------
extern "C" void kernel_launch(void* const* d_in, const int* in_sizes, int n_in,
                              void* d_out, int out_size)
{
    const float* ngram_emb     = (const float*)d_in[0];
    const float* latent        = (const float*)d_in[1];
    const float* special       = (const float*)d_in[2];
    const int*   ngram_ids     = (const int*)  d_in[3];
    const int*   ngram_offsets = (const int*)  d_in[4];
    const int*   x             = (const int*)  d_in[5];

    int n_pos    = in_sizes[5];
    int n_words  = in_sizes[4];
    int n_ngtot  = in_sizes[3];
    int n_latent = in_sizes[1] / DIM;
    if (n_pos > MAX_POS) n_pos = MAX_POS;
    if (n_latent > MAX_LT * 128) n_latent = MAX_LT * 128;

    float* out = (float*)d_out;

    int gm = (n_pos + 127) / 128;
    int TT = (n_latent + 127) / 128;
    int rows_pad = TT * 128;

    bag_kernel<<<gm * 128, DIM>>>(ngram_emb, ngram_ids, ngram_offsets, x,
                                  n_pos, n_ngtot, n_words);

    conv_latent<<<(rows_pad * DIM + 255) / 256, 256>>>(latent, n_latent, rows_pad);

    const int smem_bytes = 4 * 128 * STRIDE * 2;   // 139264 B
    cudaFuncSetAttribute(attn_mma, cudaFuncAttributeMaxDynamicSharedMemorySize, smem_bytes);
    attn_mma<<<dim3(gm, NSPLIT), 256, smem_bytes>>>(n_pos, n_latent);

    combine_kernel<<<n_pos, DIM>>>(special, x, out, n_pos);
}

// round 4
// speedup vs baseline: 12.0619x; 1.1114x over previous
#include <cuda_runtime.h>
#include <cuda_bf16.h>
#include <math.h>
#include <stdint.h>

#define DIM       128
#define NSPECIAL  4
#define MAX_POS   8192
#define MAX_LT    80
#define NSPLIT    2
#define STRIDE    136          // padded smem row stride (bf16 elems)
#define NSTAGE    3

// ---- static device scratch ----
__device__ __align__(16) float          g_lang [MAX_POS * DIM];
__device__ __align__(16) __nv_bfloat16  g_langb[MAX_POS * DIM];
__device__ __align__(16) __nv_bfloat16  g_Lb   [MAX_LT * 128 * DIM];   // [tile][lat][dim]
__device__ __align__(16) float          g_O    [NSPLIT][MAX_POS * DIM];
__device__ float                        g_z    [NSPLIT][2][MAX_POS];

// ---------------------------------------------------------------------------
// PTX helpers (all proven in R2)
// ---------------------------------------------------------------------------
__device__ __forceinline__ void ldmx4(uint32_t* r, uint32_t addr) {
    asm volatile("ldmatrix.sync.aligned.m8n8.x4.shared.b16 {%0,%1,%2,%3},[%4];\n"
        : "=r"(r[0]), "=r"(r[1]), "=r"(r[2]), "=r"(r[3]) : "r"(addr));
}
__device__ __forceinline__ void ldmx4t(uint32_t* r, uint32_t addr) {
    asm volatile("ldmatrix.sync.aligned.m8n8.x4.trans.shared.b16 {%0,%1,%2,%3},[%4];\n"
        : "=r"(r[0]), "=r"(r[1]), "=r"(r[2]), "=r"(r[3]) : "r"(addr));
}
__device__ __forceinline__ void mma16816(float* d, const uint32_t* a, const uint32_t* b) {
    asm volatile(
        "mma.sync.aligned.m16n8k16.row.col.f32.bf16.bf16.f32 "
        "{%0,%1,%2,%3},{%4,%5,%6,%7},{%8,%9},{%0,%1,%2,%3};\n"
        : "+f"(d[0]), "+f"(d[1]), "+f"(d[2]), "+f"(d[3])
        : "r"(a[0]), "r"(a[1]), "r"(a[2]), "r"(a[3]), "r"(b[0]), "r"(b[1]));
}
__device__ __forceinline__ void mma16816u(uint32_t* d, const uint32_t* a, const uint32_t* b) {
    asm volatile(
        "mma.sync.aligned.m16n8k16.row.col.f32.bf16.bf16.f32 "
        "{%0,%1,%2,%3},{%4,%5,%6,%7},{%8,%9},{%0,%1,%2,%3};\n"
        : "+r"(d[0]), "+r"(d[1]), "+r"(d[2]), "+r"(d[3])
        : "r"(a[0]), "r"(a[1]), "r"(a[2]), "r"(a[3]), "r"(b[0]), "r"(b[1]));
}
__device__ __forceinline__ void cpa16(uint32_t smem_dst, const void* gsrc) {
    asm volatile("cp.async.cg.shared.global [%0], [%1], 16;\n" :: "r"(smem_dst), "l"(gsrc));
}
#define CPA_COMMIT()  asm volatile("cp.async.commit_group;\n" ::: "memory")
#define CPA_WAIT0()   asm volatile("cp.async.wait_group 0;\n" ::: "memory")
#define CPA_WAIT1()   asm volatile("cp.async.wait_group 1;\n" ::: "memory")

__device__ __forceinline__ uint32_t pack_bf2(float a, float b) {
    uint16_t x = __bfloat16_as_ushort(__float2bfloat16_rn(a));
    uint16_t y = __bfloat16_as_ushort(__float2bfloat16_rn(b));
    return (uint32_t)x | ((uint32_t)y << 16);
}

// ---------------------------------------------------------------------------
// Kernel 1: EmbeddingBag(sum) + tanh (fp32 + bf16), padded rows -> 0
// ---------------------------------------------------------------------------
__global__ void bag_kernel(const float* __restrict__ ngram_emb,
                           const int*   __restrict__ ngram_ids,
                           const int*   __restrict__ ngram_offsets,
                           const int*   __restrict__ x,
                           int n_pos, int n_ngram_total, int n_words)
{
    int pos = blockIdx.x;
    int d   = threadIdx.x;
    float val = 0.0f;
    if (pos < n_pos) {
        int t = x[pos];
        if (t >= NSPECIAL) {
            int v   = t - NSPECIAL;
            int off = ngram_offsets[v];
            int end = (v + 1 < n_words) ? ngram_offsets[v + 1] : n_ngram_total;
            float a0 = 0.f, a1 = 0.f, a2 = 0.f, a3 = 0.f;
            int j = off;
            for (; j + 3 < end; j += 4) {
                int i0 = ngram_ids[j], i1 = ngram_ids[j+1];
                int i2 = ngram_ids[j+2], i3 = ngram_ids[j+3];
                a0 += ngram_emb[(size_t)i0 * DIM + d];
                a1 += ngram_emb[(size_t)i1 * DIM + d];
                a2 += ngram_emb[(size_t)i2 * DIM + d];
                a3 += ngram_emb[(size_t)i3 * DIM + d];
            }
            for (; j < end; ++j)
                a0 += ngram_emb[(size_t)ngram_ids[j] * DIM + d];
            val = tanhf((a0 + a1) + (a2 + a3));
        }
    }
    g_lang [pos * DIM + d] = val;
    g_langb[pos * DIM + d] = __float2bfloat16_rn(val);
}

// ---------------------------------------------------------------------------
// Kernel 2: latent -> bf16, zero-padded to full 128-row tiles
// ---------------------------------------------------------------------------
__global__ void conv_latent(const float* __restrict__ latent, int n_latent, int total)
{
    int idx = blockIdx.x * 256 + threadIdx.x;
    if (idx >= total) return;
    int r = idx >> 7;
    g_Lb[idx] = __float2bfloat16_rn(r < n_latent ? latent[idx] : 0.f);
}

// ---------------------------------------------------------------------------
// Kernel 3: register-P flash attention on HMMA.
// CTA = 128 tokens, 256 threads = 8 warps (wm 0..3 token blocks, wn 0..1
// latent halves). Per tile: GEMM1 -> exp in regs -> GEMM2 (A from regs).
// One __syncthreads per tile (cp.async stage rotation).
// ---------------------------------------------------------------------------
__global__ __launch_bounds__(256, 1)
void attn_mma2(int n_pos, int n_latent)
{
    extern __shared__ __nv_bfloat16 sm[];
    __nv_bfloat16* lang_sm = sm;                         // 128*STRIDE

    const int tid  = threadIdx.x;
    const int lane = tid & 31;
    const int warp = tid >> 5;
    const int wm   = warp & 3;       // token rows wm*32..+31
    const int wn   = warp >> 2;      // latent half (64 lats) within tile
    const int pos0 = blockIdx.x * 128;
    const int split = blockIdx.y;

    const int TT   = (n_latent + 127) >> 7;
    const int half = (TT + 1) >> 1;
    const int t0   = split ? half : 0;
    const int cnt  = split ? (TT - half) : half;

    const uint32_t lang_u = (uint32_t)__cvta_generic_to_shared(lang_sm);
    uint32_t stg_u[NSTAGE];
#pragma unroll
    for (int s = 0; s < NSTAGE; ++s)
        stg_u[s] = lang_u + (1 + s) * 128 * STRIDE * 2;

    // ---- load lang tile ----
    for (int ch = tid; ch < 2048; ch += 256) {
        int r = ch >> 4, c = (ch & 15) << 3;
        *(uint4*)&lang_sm[r * STRIDE + c] = *(const uint4*)&g_langb[(size_t)(pos0 + r) * DIM + c];
    }

    // ---- prologue: issue tiles t0, t0+1 ----
#pragma unroll 1
    for (int pf = 0; pf < 2; ++pf) {
        if (pf < cnt) {
            const __nv_bfloat16* src = g_Lb + (size_t)(t0 + pf) * 128 * DIM;
            uint32_t dst = stg_u[pf];
            for (int ch = tid; ch < 2048; ch += 256) {
                int r = ch >> 4, c = (ch & 15) << 3;
                cpa16(dst + (r * STRIDE + c) * 2, src + r * DIM + c);
            }
            CPA_COMMIT();
        }
    }

    float o[2][16][4];
    float zacc[2][2];
#pragma unroll
    for (int mi = 0; mi < 2; ++mi) {
        zacc[mi][0] = 0.f; zacc[mi][1] = 0.f;
#pragma unroll
        for (int nj = 0; nj < 16; ++nj)
#pragma unroll
            for (int q = 0; q < 4; ++q) o[mi][nj][q] = 0.f;
    }

    const int lr = lane & 15;
    const int lc = (lane & 16) >> 1;   // 0 or 8

    for (int t = 0; t < cnt; ++t) {
        if (t + 1 < cnt) CPA_WAIT1(); else CPA_WAIT0();
        __syncthreads();                       // tile t visible; stage (t+2)%3 free
        if (t + 2 < cnt) {
            const __nv_bfloat16* src = g_Lb + (size_t)(t0 + t + 2) * 128 * DIM;
            uint32_t dst = stg_u[(t + 2) % NSTAGE];
            for (int ch = tid; ch < 2048; ch += 256) {
                int r = ch >> 4, c = (ch & 15) << 3;
                cpa16(dst + (r * STRIDE + c) * 2, src + r * DIM + c);
            }
            CPA_COMMIT();
        }
        const uint32_t Lst = stg_u[t % NSTAGE];

        // ---- GEMM1: s[32 tok x 64 lat(own)] = lang @ L^T ----
        float s[2][8][4];
#pragma unroll
        for (int mi = 0; mi < 2; ++mi)
#pragma unroll
            for (int j = 0; j < 8; ++j)
#pragma unroll
                for (int q = 0; q < 4; ++q) s[mi][j][q] = 0.f;

#pragma unroll
        for (int ks = 0; ks < 8; ++ks) {
            uint32_t a[2][4];
#pragma unroll
            for (int mi = 0; mi < 2; ++mi)
                ldmx4(a[mi], lang_u + ((wm * 32 + mi * 16 + lr) * STRIDE + ks * 16 + lc) * 2);
            uint32_t b[8][2];
#pragma unroll
            for (int ni = 0; ni < 4; ++ni) {
                uint32_t r4[4];
                ldmx4(r4, Lst + ((wn * 64 + ni * 16 + lr) * STRIDE + ks * 16 + lc) * 2);
                b[2 * ni][0] = r4[0]; b[2 * ni][1] = r4[2];
                b[2 * ni + 1][0] = r4[1]; b[2 * ni + 1][1] = r4[3];
            }
#pragma unroll
            for (int mi = 0; mi < 2; ++mi)
#pragma unroll
                for (int j = 0; j < 8; ++j)
                    mma16816(s[mi][j], a[mi], b[j]);
        }

        // ---- exp in registers -> A fragments for GEMM2 ----
        // acc(c0..c3) of block j maps exactly onto A-frag regs of k-block j.
        uint32_t pk[2][4][4];
        const int lbase = (t0 + t) * 128 + wn * 64;
        if (lbase + 64 <= n_latent) {
#pragma unroll
            for (int mi = 0; mi < 2; ++mi)
#pragma unroll
                for (int j = 0; j < 8; ++j) {
                    float e0 = __expf(s[mi][j][0]);
                    float e1 = __expf(s[mi][j][1]);
                    float e2 = __expf(s[mi][j][2]);
                    float e3 = __expf(s[mi][j][3]);
                    zacc[mi][0] += e0 + e1;
                    zacc[mi][1] += e2 + e3;
                    pk[mi][j >> 1][(j & 1) * 2]     = pack_bf2(e0, e1);
                    pk[mi][j >> 1][(j & 1) * 2 + 1] = pack_bf2(e2, e3);
                }
        } else {
            const int c2 = (lane & 3) << 1;
#pragma unroll
            for (int mi = 0; mi < 2; ++mi)
#pragma unroll
                for (int j = 0; j < 8; ++j) {
                    int g0 = lbase + 8 * j + c2;
                    float e0 = (g0     < n_latent) ? __expf(s[mi][j][0]) : 0.f;
                    float e1 = (g0 + 1 < n_latent) ? __expf(s[mi][j][1]) : 0.f;
                    float e2 = (g0     < n_latent) ? __expf(s[mi][j][2]) : 0.f;
                    float e3 = (g0 + 1 < n_latent) ? __expf(s[mi][j][3]) : 0.f;
                    zacc[mi][0] += e0 + e1;
                    zacc[mi][1] += e2 + e3;
                    pk[mi][j >> 1][(j & 1) * 2]     = pack_bf2(e0, e1);
                    pk[mi][j >> 1][(j & 1) * 2 + 1] = pack_bf2(e2, e3);
                }
        }

        // ---- GEMM2: o[32 tok x 128 dim] += P(regs) @ L (k = own 64 lats) ----
#pragma unroll
        for (int kk = 0; kk < 4; ++kk) {
            uint32_t b[16][2];
#pragma unroll
            for (int ni = 0; ni < 8; ++ni) {
                uint32_t r4[4];
                ldmx4t(r4, Lst + ((wn * 64 + kk * 16 + lr) * STRIDE + ni * 16 + lc) * 2);
                b[2 * ni][0] = r4[0]; b[2 * ni][1] = r4[1];
                b[2 * ni + 1][0] = r4[2]; b[2 * ni + 1][1] = r4[3];
            }
#pragma unroll
            for (int mi = 0; mi < 2; ++mi)
#pragma unroll
                for (int nj = 0; nj < 16; ++nj)
                    mma16816(o[mi][nj], pk[mi][kk], b[nj]);
        }
    }

    // ---- z: reduce over quad lanes, write per (split, wn) partial ----
#pragma unroll
    for (int mi = 0; mi < 2; ++mi)
#pragma unroll
        for (int h = 0; h < 2; ++h) {
            float zz = zacc[mi][h];
            zz += __shfl_xor_sync(0xffffffffu, zz, 1);
            zz += __shfl_xor_sync(0xffffffffu, zz, 2);
            if ((lane & 3) == 0) {
                int r = pos0 + wm * 32 + mi * 16 + (lane >> 2) + h * 8;
                g_z[split][wn][r] = zz;
            }
        }

    // ---- O combine across the wn pair via smem overlay on the stages ----
    float* ored = (float*)(sm + 128 * STRIDE);       // 64 KB overlay
    __syncthreads();                                 // all tile reads done
    const int r0 = wm * 32 + (lane >> 2);
    const int c0 = (lane & 3) << 1;
    if (wn == 0) {
#pragma unroll
        for (int mi = 0; mi < 2; ++mi)
#pragma unroll
            for (int nj = 0; nj < 16; ++nj) {
                *(float2*)&ored[(r0 + mi * 16)     * 128 + nj * 8 + c0] = make_float2(o[mi][nj][0], o[mi][nj][1]);
                *(float2*)&ored[(r0 + mi * 16 + 8) * 128 + nj * 8 + c0] = make_float2(o[mi][nj][2], o[mi][nj][3]);
            }
    }
    __syncthreads();
    if (wn == 1) {
        float* dst = g_O[split] + (size_t)pos0 * DIM;
#pragma unroll
        for (int mi = 0; mi < 2; ++mi)
#pragma unroll
            for (int nj = 0; nj < 16; ++nj) {
                int ra = (r0 + mi * 16) * 128 + nj * 8 + c0;
                int rb = ra + 8 * 128;
                float2 pa = *(float2*)&ored[ra];
                float2 pb = *(float2*)&ored[rb];
                *(float2*)&dst[ra] = make_float2(pa.x + o[mi][nj][0], pa.y + o[mi][nj][1]);
                *(float2*)&dst[rb] = make_float2(pb.x + o[mi][nj][2], pb.y + o[mi][nj][3]);
            }
    }
}

// ---------------------------------------------------------------------------
// Kernel 4: combine splits + lang add + special override
// ---------------------------------------------------------------------------
__global__ void combine_kernel(const float* __restrict__ special,
                               const int*   __restrict__ x,
                               float*       __restrict__ out,
                               int n_pos)
{
    int pos = blockIdx.x;
    int d   = threadIdx.x;
    if (pos >= n_pos) return;
    int t = x[pos];
    float v;
    if (t < NSPECIAL) {
        v = special[t * DIM + d];
    } else {
        float z = g_z[0][0][pos] + g_z[0][1][pos] + g_z[1][0][pos] + g_z[1][1][pos];
        float O = g_O[0][pos * DIM + d] + g_O[1][pos * DIM + d];
        v = g_lang[pos * DIM + d] + O / z;
    }
    out[pos * DIM + d] = v;
}

// ---------------------------------------------------------------------------
extern "C" void kernel_launch(void* const* d_in, const int* in_sizes, int n_in,
                              void* d_out, int out_size)
{
    const float* ngram_emb     = (const float*)d_in[0];
    const float* latent        = (const float*)d_in[1];
    const float* special       = (const float*)d_in[2];
    const int*   ngram_ids     = (const int*)  d_in[3];
    const int*   ngram_offsets = (const int*)  d_in[4];
    const int*   x             = (const int*)  d_in[5];

    int n_pos    = in_sizes[5];
    int n_words  = in_sizes[4];
    int n_ngtot  = in_sizes[3];
    int n_latent = in_sizes[1] / DIM;
    if (n_pos > MAX_POS) n_pos = MAX_POS;
    if (n_latent > MAX_LT * 128) n_latent = MAX_LT * 128;

    float* out = (float*)d_out;

    int gm = (n_pos + 127) / 128;
    int TT = (n_latent + 127) / 128;
    int total = TT * 128 * DIM;

    bag_kernel<<<gm * 128, DIM>>>(ngram_emb, ngram_ids, ngram_offsets, x,
                                  n_pos, n_ngtot, n_words);

    conv_latent<<<(total + 255) / 256, 256>>>(latent, n_latent, total);

    const int smem_bytes = (1 + NSTAGE) * 128 * STRIDE * 2;   // 139264 B
    cudaFuncSetAttribute(attn_mma2,
                         cudaFuncAttributeMaxDynamicSharedMemorySize, smem_bytes);
    attn_mma2<<<dim3(gm, NSPLIT), 256, smem_bytes>>>(n_pos, n_latent);

    combine_kernel<<<n_pos, DIM>>>(special, x, out, n_pos);
}

// round 5
// speedup vs baseline: 12.0764x; 1.0012x over previous
#include <cuda_runtime.h>
#include <cuda_bf16.h>
#include <math.h>
#include <stdint.h>

#define DIM       128
#define NSPECIAL  4
#define MAX_POS   8192
#define MAX_LT    80
#define NSPLIT    2
#define STRIDE    136          // padded smem row stride (bf16 elems)
#define NSTAGE    3

// ---- static device scratch ----
__device__ __align__(16) float          g_lang [MAX_POS * DIM];
__device__ __align__(16) __nv_bfloat16  g_langb[MAX_POS * DIM];
__device__ __align__(16) __nv_bfloat16  g_Lb   [MAX_LT * 128 * DIM];   // [tile][lat][dim]
__device__ __align__(16) float          g_O    [NSPLIT][MAX_POS * DIM];
__device__ float                        g_z    [NSPLIT][2][MAX_POS];

// ---------------------------------------------------------------------------
// PTX helpers (all proven in R2)
// ---------------------------------------------------------------------------
__device__ __forceinline__ void ldmx4(uint32_t* r, uint32_t addr) {
    asm volatile("ldmatrix.sync.aligned.m8n8.x4.shared.b16 {%0,%1,%2,%3},[%4];\n"
        : "=r"(r[0]), "=r"(r[1]), "=r"(r[2]), "=r"(r[3]) : "r"(addr));
}
__device__ __forceinline__ void ldmx4t(uint32_t* r, uint32_t addr) {
    asm volatile("ldmatrix.sync.aligned.m8n8.x4.trans.shared.b16 {%0,%1,%2,%3},[%4];\n"
        : "=r"(r[0]), "=r"(r[1]), "=r"(r[2]), "=r"(r[3]) : "r"(addr));
}
__device__ __forceinline__ void mma16816(float* d, const uint32_t* a, const uint32_t* b) {
    asm volatile(
        "mma.sync.aligned.m16n8k16.row.col.f32.bf16.bf16.f32 "
        "{%0,%1,%2,%3},{%4,%5,%6,%7},{%8,%9},{%0,%1,%2,%3};\n"
        : "+f"(d[0]), "+f"(d[1]), "+f"(d[2]), "+f"(d[3])
        : "r"(a[0]), "r"(a[1]), "r"(a[2]), "r"(a[3]), "r"(b[0]), "r"(b[1]));
}
__device__ __forceinline__ void mma16816u(uint32_t* d, const uint32_t* a, const uint32_t* b) {
    asm volatile(
        "mma.sync.aligned.m16n8k16.row.col.f32.bf16.bf16.f32 "
        "{%0,%1,%2,%3},{%4,%5,%6,%7},{%8,%9},{%0,%1,%2,%3};\n"
        : "+r"(d[0]), "+r"(d[1]), "+r"(d[2]), "+r"(d[3])
        : "r"(a[0]), "r"(a[1]), "r"(a[2]), "r"(a[3]), "r"(b[0]), "r"(b[1]));
}
__device__ __forceinline__ void cpa16(uint32_t smem_dst, const void* gsrc) {
    asm volatile("cp.async.cg.shared.global [%0], [%1], 16;\n" :: "r"(smem_dst), "l"(gsrc));
}
#define CPA_COMMIT()  asm volatile("cp.async.commit_group;\n" ::: "memory")
#define CPA_WAIT0()   asm volatile("cp.async.wait_group 0;\n" ::: "memory")
#define CPA_WAIT1()   asm volatile("cp.async.wait_group 1;\n" ::: "memory")

__device__ __forceinline__ uint32_t pack_bf2(float a, float b) {
    uint16_t x = __bfloat16_as_ushort(__float2bfloat16_rn(a));
    uint16_t y = __bfloat16_as_ushort(__float2bfloat16_rn(b));
    return (uint32_t)x | ((uint32_t)y << 16);
}

// ---------------------------------------------------------------------------
// Kernel 1: EmbeddingBag(sum) + tanh (fp32 + bf16), padded rows -> 0
// ---------------------------------------------------------------------------
__global__ void bag_kernel(const float* __restrict__ ngram_emb,
                           const int*   __restrict__ ngram_ids,
                           const int*   __restrict__ ngram_offsets,
                           const int*   __restrict__ x,
                           int n_pos, int n_ngram_total, int n_words)
{
    int pos = blockIdx.x;
    int d   = threadIdx.x;
    float val = 0.0f;
    if (pos < n_pos) {
        int t = x[pos];
        if (t >= NSPECIAL) {
            int v   = t - NSPECIAL;
            int off = ngram_offsets[v];
            int end = (v + 1 < n_words) ? ngram_offsets[v + 1] : n_ngram_total;
            float a0 = 0.f, a1 = 0.f, a2 = 0.f, a3 = 0.f;
            int j = off;
            for (; j + 3 < end; j += 4) {
                int i0 = ngram_ids[j], i1 = ngram_ids[j+1];
                int i2 = ngram_ids[j+2], i3 = ngram_ids[j+3];
                a0 += ngram_emb[(size_t)i0 * DIM + d];
                a1 += ngram_emb[(size_t)i1 * DIM + d];
                a2 += ngram_emb[(size_t)i2 * DIM + d];
                a3 += ngram_emb[(size_t)i3 * DIM + d];
            }
            for (; j < end; ++j)
                a0 += ngram_emb[(size_t)ngram_ids[j] * DIM + d];
            val = tanhf((a0 + a1) + (a2 + a3));
        }
    }
    g_lang [pos * DIM + d] = val;
    g_langb[pos * DIM + d] = __float2bfloat16_rn(val);
}

// ---------------------------------------------------------------------------
// Kernel 2: latent -> bf16, zero-padded to full 128-row tiles
// ---------------------------------------------------------------------------
__global__ void conv_latent(const float* __restrict__ latent, int n_latent, int total)
{
    int idx = blockIdx.x * 256 + threadIdx.x;
    if (idx >= total) return;
    int r = idx >> 7;
    g_Lb[idx] = __float2bfloat16_rn(r < n_latent ? latent[idx] : 0.f);
}

// ---------------------------------------------------------------------------
// Kernel 3: register-P flash attention on HMMA.
// CTA = 128 tokens, 256 threads = 8 warps (wm 0..3 token blocks, wn 0..1
// latent halves). Per tile: GEMM1 -> exp in regs -> GEMM2 (A from regs).
// One __syncthreads per tile (cp.async stage rotation).
// ---------------------------------------------------------------------------
__global__ __launch_bounds__(256, 1)
void attn_mma2(int n_pos, int n_latent)
{
    extern __shared__ __nv_bfloat16 sm[];
    __nv_bfloat16* lang_sm = sm;                         // 128*STRIDE

    const int tid  = threadIdx.x;
    const int lane = tid & 31;
    const int warp = tid >> 5;
    const int wm   = warp & 3;       // token rows wm*32..+31
    const int wn   = warp >> 2;      // latent half (64 lats) within tile
    const int pos0 = blockIdx.x * 128;
    const int split = blockIdx.y;

    const int TT   = (n_latent + 127) >> 7;
    const int half = (TT + 1) >> 1;
    const int t0   = split ? half : 0;
    const int cnt  = split ? (TT - half) : half;

    const uint32_t lang_u = (uint32_t)__cvta_generic_to_shared(lang_sm);
    uint32_t stg_u[NSTAGE];
#pragma unroll
    for (int s = 0; s < NSTAGE; ++s)
        stg_u[s] = lang_u + (1 + s) * 128 * STRIDE * 2;

    // ---- load lang tile ----
    for (int ch = tid; ch < 2048; ch += 256) {
        int r = ch >> 4, c = (ch & 15) << 3;
        *(uint4*)&lang_sm[r * STRIDE + c] = *(const uint4*)&g_langb[(size_t)(pos0 + r) * DIM + c];
    }

    // ---- prologue: issue tiles t0, t0+1 ----
#pragma unroll 1
    for (int pf = 0; pf < 2; ++pf) {
        if (pf < cnt) {
            const __nv_bfloat16* src = g_Lb + (size_t)(t0 + pf) * 128 * DIM;
            uint32_t dst = stg_u[pf];
            for (int ch = tid; ch < 2048; ch += 256) {
                int r = ch >> 4, c = (ch & 15) << 3;
                cpa16(dst + (r * STRIDE + c) * 2, src + r * DIM + c);
            }
            CPA_COMMIT();
        }
    }

    float o[2][16][4];
    float zacc[2][2];
#pragma unroll
    for (int mi = 0; mi < 2; ++mi) {
        zacc[mi][0] = 0.f; zacc[mi][1] = 0.f;
#pragma unroll
        for (int nj = 0; nj < 16; ++nj)
#pragma unroll
            for (int q = 0; q < 4; ++q) o[mi][nj][q] = 0.f;
    }

    const int lr = lane & 15;
    const int lc = (lane & 16) >> 1;   // 0 or 8

    for (int t = 0; t < cnt; ++t) {
        if (t + 1 < cnt) CPA_WAIT1(); else CPA_WAIT0();
        __syncthreads();                       // tile t visible; stage (t+2)%3 free
        if (t + 2 < cnt) {
            const __nv_bfloat16* src = g_Lb + (size_t)(t0 + t + 2) * 128 * DIM;
            uint32_t dst = stg_u[(t + 2) % NSTAGE];
            for (int ch = tid; ch < 2048; ch += 256) {
                int r = ch >> 4, c = (ch & 15) << 3;
                cpa16(dst + (r * STRIDE + c) * 2, src + r * DIM + c);
            }
            CPA_COMMIT();
        }
        const uint32_t Lst = stg_u[t % NSTAGE];

        // ---- GEMM1: s[32 tok x 64 lat(own)] = lang @ L^T ----
        float s[2][8][4];
#pragma unroll
        for (int mi = 0; mi < 2; ++mi)
#pragma unroll
            for (int j = 0; j < 8; ++j)
#pragma unroll
                for (int q = 0; q < 4; ++q) s[mi][j][q] = 0.f;

#pragma unroll
        for (int ks = 0; ks < 8; ++ks) {
            uint32_t a[2][4];
#pragma unroll
            for (int mi = 0; mi < 2; ++mi)
                ldmx4(a[mi], lang_u + ((wm * 32 + mi * 16 + lr) * STRIDE + ks * 16 + lc) * 2);
            uint32_t b[8][2];
#pragma unroll
            for (int ni = 0; ni < 4; ++ni) {
                uint32_t r4[4];
                ldmx4(r4, Lst + ((wn * 64 + ni * 16 + lr) * STRIDE + ks * 16 + lc) * 2);
                b[2 * ni][0] = r4[0]; b[2 * ni][1] = r4[2];
                b[2 * ni + 1][0] = r4[1]; b[2 * ni + 1][1] = r4[3];
            }
#pragma unroll
            for (int mi = 0; mi < 2; ++mi)
#pragma unroll
                for (int j = 0; j < 8; ++j)
                    mma16816(s[mi][j], a[mi], b[j]);
        }

        // ---- exp in registers -> A fragments for GEMM2 ----
        // acc(c0..c3) of block j maps exactly onto A-frag regs of k-block j.
        uint32_t pk[2][4][4];
        const int lbase = (t0 + t) * 128 + wn * 64;
        if (lbase + 64 <= n_latent) {
#pragma unroll
            for (int mi = 0; mi < 2; ++mi)
#pragma unroll
                for (int j = 0; j < 8; ++j) {
                    float e0 = __expf(s[mi][j][0]);
                    float e1 = __expf(s[mi][j][1]);
                    float e2 = __expf(s[mi][j][2]);
                    float e3 = __expf(s[mi][j][3]);
                    zacc[mi][0] += e0 + e1;
                    zacc[mi][1] += e2 + e3;
                    pk[mi][j >> 1][(j & 1) * 2]     = pack_bf2(e0, e1);
                    pk[mi][j >> 1][(j & 1) * 2 + 1] = pack_bf2(e2, e3);
                }
        } else {
            const int c2 = (lane & 3) << 1;
#pragma unroll
            for (int mi = 0; mi < 2; ++mi)
#pragma unroll
                for (int j = 0; j < 8; ++j) {
                    int g0 = lbase + 8 * j + c2;
                    float e0 = (g0     < n_latent) ? __expf(s[mi][j][0]) : 0.f;
                    float e1 = (g0 + 1 < n_latent) ? __expf(s[mi][j][1]) : 0.f;
                    float e2 = (g0     < n_latent) ? __expf(s[mi][j][2]) : 0.f;
                    float e3 = (g0 + 1 < n_latent) ? __expf(s[mi][j][3]) : 0.f;
                    zacc[mi][0] += e0 + e1;
                    zacc[mi][1] += e2 + e3;
                    pk[mi][j >> 1][(j & 1) * 2]     = pack_bf2(e0, e1);
                    pk[mi][j >> 1][(j & 1) * 2 + 1] = pack_bf2(e2, e3);
                }
        }

        // ---- GEMM2: o[32 tok x 128 dim] += P(regs) @ L (k = own 64 lats) ----
#pragma unroll
        for (int kk = 0; kk < 4; ++kk) {
            uint32_t b[16][2];
#pragma unroll
            for (int ni = 0; ni < 8; ++ni) {
                uint32_t r4[4];
                ldmx4t(r4, Lst + ((wn * 64 + kk * 16 + lr) * STRIDE + ni * 16 + lc) * 2);
                b[2 * ni][0] = r4[0]; b[2 * ni][1] = r4[1];
                b[2 * ni + 1][0] = r4[2]; b[2 * ni + 1][1] = r4[3];
            }
#pragma unroll
            for (int mi = 0; mi < 2; ++mi)
#pragma unroll
                for (int nj = 0; nj < 16; ++nj)
                    mma16816(o[mi][nj], pk[mi][kk], b[nj]);
        }
    }

    // ---- z: reduce over quad lanes, write per (split, wn) partial ----
#pragma unroll
    for (int mi = 0; mi < 2; ++mi)
#pragma unroll
        for (int h = 0; h < 2; ++h) {
            float zz = zacc[mi][h];
            zz += __shfl_xor_sync(0xffffffffu, zz, 1);
            zz += __shfl_xor_sync(0xffffffffu, zz, 2);
            if ((lane & 3) == 0) {
                int r = pos0 + wm * 32 + mi * 16 + (lane >> 2) + h * 8;
                g_z[split][wn][r] = zz;
            }
        }

    // ---- O combine across the wn pair via smem overlay on the stages ----
    float* ored = (float*)(sm + 128 * STRIDE);       // 64 KB overlay
    __syncthreads();                                 // all tile reads done
    const int r0 = wm * 32 + (lane >> 2);
    const int c0 = (lane & 3) << 1;
    if (wn == 0) {
#pragma unroll
        for (int mi = 0; mi < 2; ++mi)
#pragma unroll
            for (int nj = 0; nj < 16; ++nj) {
                *(float2*)&ored[(r0 + mi * 16)     * 128 + nj * 8 + c0] = make_float2(o[mi][nj][0], o[mi][nj][1]);
                *(float2*)&ored[(r0 + mi * 16 + 8) * 128 + nj * 8 + c0] = make_float2(o[mi][nj][2], o[mi][nj][3]);
            }
    }
    __syncthreads();
    if (wn == 1) {
        float* dst = g_O[split] + (size_t)pos0 * DIM;
#pragma unroll
        for (int mi = 0; mi < 2; ++mi)
#pragma unroll
            for (int nj = 0; nj < 16; ++nj) {
                int ra = (r0 + mi * 16) * 128 + nj * 8 + c0;
                int rb = ra + 8 * 128;
                float2 pa = *(float2*)&ored[ra];
                float2 pb = *(float2*)&ored[rb];
                *(float2*)&dst[ra] = make_float2(pa.x + o[mi][nj][0], pa.y + o[mi][nj][1]);
                *(float2*)&dst[rb] = make_float2(pb.x + o[mi][nj][2], pb.y + o[mi][nj][3]);
            }
    }
}

// ---------------------------------------------------------------------------
// Kernel 4: combine splits + lang add + special override
// ---------------------------------------------------------------------------
__global__ void combine_kernel(const float* __restrict__ special,
                               const int*   __restrict__ x,
                               float*       __restrict__ out,
                               int n_pos)
{
    int pos = blockIdx.x;
    int d   = threadIdx.x;
    if (pos >= n_pos) return;
    int t = x[pos];
    float v;
    if (t < NSPECIAL) {
        v = special[t * DIM + d];
    } else {
        float z = g_z[0][0][pos] + g_z[0][1][pos] + g_z[1][0][pos] + g_z[1][1][pos];
        float O = g_O[0][pos * DIM + d] + g_O[1][pos * DIM + d];
        v = g_lang[pos * DIM + d] + O / z;
    }
    out[pos * DIM + d] = v;
}

// ---------------------------------------------------------------------------
extern "C" void kernel_launch(void* const* d_in, const int* in_sizes, int n_in,
                              void* d_out, int out_size)
{
    const float* ngram_emb     = (const float*)d_in[0];
    const float* latent        = (const float*)d_in[1];
    const float* special       = (const float*)d_in[2];
    const int*   ngram_ids     = (const int*)  d_in[3];
    const int*   ngram_offsets = (const int*)  d_in[4];
    const int*   x             = (const int*)  d_in[5];

    int n_pos    = in_sizes[5];
    int n_words  = in_sizes[4];
    int n_ngtot  = in_sizes[3];
    int n_latent = in_sizes[1] / DIM;
    if (n_pos > MAX_POS) n_pos = MAX_POS;
    if (n_latent > MAX_LT * 128) n_latent = MAX_LT * 128;

    float* out = (float*)d_out;

    int gm = (n_pos + 127) / 128;
    int TT = (n_latent + 127) / 128;
    int total = TT * 128 * DIM;

    bag_kernel<<<gm * 128, DIM>>>(ngram_emb, ngram_ids, ngram_offsets, x,
                                  n_pos, n_ngtot, n_words);

    conv_latent<<<(total + 255) / 256, 256>>>(latent, n_latent, total);

    const int smem_bytes = (1 + NSTAGE) * 128 * STRIDE * 2;   // 139264 B
    cudaFuncSetAttribute(attn_mma2,
                         cudaFuncAttributeMaxDynamicSharedMemorySize, smem_bytes);
    attn_mma2<<<dim3(gm, NSPLIT), 256, smem_bytes>>>(n_pos, n_latent);

    combine_kernel<<<n_pos, DIM>>>(special, x, out, n_pos);
}